// round 1
// baseline (speedup 1.0000x reference)
#include <cuda_runtime.h>
#include <math.h>
#include <stdint.h>

#define NV 8192      // variable nodes
#define MC 4096      // check nodes
#define DV 3         // layers
#define EE (DV*NV)   // edges = 24576
#define BB 512       // batch
#define TT 10        // iterations

// ---------------- device scratch (static, no allocation) ----------------
__device__ float g_llr_t[NV * BB];   // llr transposed [N, B]   16 MB
__device__ float g_v2c[EE * BB];     // v2c messages   [E, B]   48 MB
__device__ float g_c2v[EE * BB];     // c2v messages   [E, B]   48 MB
__device__ float g_post[NV * BB];    // posterior      [N, B]   16 MB
__device__ int   g_inv[DV * NV];     // inverse permutations

// ---------------- transpose llr [B,N] -> [N,B] ----------------
__global__ void k_transpose_in(const float* __restrict__ llr) {
    __shared__ float tile[32][33];
    int n0 = blockIdx.x * 32;
    int b0 = blockIdx.y * 32;
    // read llr[b, n]: n fastest across threadIdx.x -> coalesced
    tile[threadIdx.y][threadIdx.x] = llr[(b0 + threadIdx.y) * NV + (n0 + threadIdx.x)];
    __syncthreads();
    // write llr_t[n, b]: b fastest -> coalesced
    g_llr_t[(n0 + threadIdx.y) * BB + (b0 + threadIdx.x)] = tile[threadIdx.x][threadIdx.y];
}

// ---------------- inverse permutation build ----------------
__global__ void k_invperm(const int* __restrict__ edge_v) {
    int e = blockIdx.x * blockDim.x + threadIdx.x;
    if (e < EE) {
        int l = e >> 13;          // N = 8192 = 2^13
        int i = e & (NV - 1);
        g_inv[l * NV + edge_v[e]] = i;
    }
}

// ---------------- check-node update ----------------
// grid: M*2 blocks of 256; block covers one check m, half a batch row
__global__ void __launch_bounds__(256) k_check(const int* __restrict__ edge_v,
                                               const float* __restrict__ beta,
                                               int t) {
    int m = blockIdx.x >> 1;
    int b = ((blockIdx.x & 1) << 8) | threadIdx.x;

    float v2c[6];
    if (t == 0) {
        // v2c init = llr at each edge: gather from llr_t via edge_v (uniform idx per block)
#pragma unroll
        for (int l = 0; l < 6; l++) {
            int i = 2 * m + (l & 1);
            int v = __ldg(&edge_v[(l >> 1) * NV + i]);
            v2c[l] = g_llr_t[v * BB + b];
        }
    } else {
#pragma unroll
        for (int l = 0; l < 6; l++) {
            int e = (l >> 1) * NV + 2 * m + (l & 1);
            v2c[l] = g_v2c[e * BB + b];
        }
    }

    float m1 = INFINITY, m2 = INFINITY;
    int arg = 0, par = 0;
    bool anyzero = false;
#pragma unroll
    for (int l = 0; l < 6; l++) {
        float x = v2c[l];
        float a = fabsf(x);
        par ^= (x < 0.0f) ? 1 : 0;
        anyzero |= (a == 0.0f);
        if (a < m1) { m2 = m1; m1 = a; arg = l; }
        else if (a < m2) { m2 = a; }
    }

    float bt = __ldg(&beta[t]);
#pragma unroll
    for (int l = 0; l < 6; l++) {
        float mag = (l == arg) ? m2 : m1;
        int neg = par ^ ((v2c[l] < 0.0f) ? 1 : 0);
        float c = bt * (neg ? -mag : mag);
        if (anyzero) c = 0.0f;
        int e = (l >> 1) * NV + 2 * m + (l & 1);
        g_c2v[e * BB + b] = c;
    }
}

// ---------------- variable-node update ----------------
// grid: N*2 blocks of 256; block covers one variable v, half a batch row
__global__ void __launch_bounds__(256) k_var(const float* __restrict__ alpha,
                                             int t, int last) {
    int v = blockIdx.x >> 1;
    int b = ((blockIdx.x & 1) << 8) | threadIdx.x;

    int i0 = __ldg(&g_inv[0 * NV + v]);
    int i1 = __ldg(&g_inv[1 * NV + v]);
    int i2 = __ldg(&g_inv[2 * NV + v]);
    int e0 = 0 * NV + i0;
    int e1 = 1 * NV + i1;
    int e2 = 2 * NV + i2;

    float c0 = g_c2v[e0 * BB + b];
    float c1 = g_c2v[e1 * BB + b];
    float c2 = g_c2v[e2 * BB + b];
    float s = c0 + c1 + c2;
    float l = g_llr_t[v * BB + b];

    if (last) {
        g_post[v * BB + b] = l + s;   // posterior: NO alpha scaling
    } else {
        float at = __ldg(&alpha[t]);
        float base = l;
        g_v2c[e0 * BB + b] = base + at * (s - c0);
        g_v2c[e1 * BB + b] = base + at * (s - c1);
        g_v2c[e2 * BB + b] = base + at * (s - c2);
    }
}

// ---------------- output: transpose posterior, emit bits + posterior ----------------
__global__ void k_out(float* __restrict__ out_f, int* __restrict__ out_i, int mode) {
    __shared__ float tile[32][33];
    int n0 = blockIdx.x * 32;
    int b0 = blockIdx.y * 32;
    // read g_post[n, b]: b fastest -> coalesced
    tile[threadIdx.y][threadIdx.x] = g_post[(n0 + threadIdx.y) * BB + (b0 + threadIdx.x)];
    __syncthreads();
    float p = tile[threadIdx.x][threadIdx.y];                // n = n0+tx, b = b0+ty
    int o = (b0 + threadIdx.y) * NV + (n0 + threadIdx.x);    // [B, N] row-major
    if (mode == 2) {
        out_f[o] = (p < 0.0f) ? 1.0f : 0.0f;   // decoded bits (first output)
        out_f[BB * NV + o] = p;                // posterior (second output)
    } else {
        out_i[o] = (p < 0.0f) ? 1 : 0;         // bits only, int32
    }
}

extern "C" void kernel_launch(void* const* d_in, const int* in_sizes, int n_in,
                              void* d_out, int out_size) {
    const float* llr    = (const float*)d_in[0];
    const int*   edge_v = (const int*)d_in[1];
    // d_in[2] = edge_c: structurally implied (i/2 per layer), unused
    const float* beta   = (const float*)d_in[3];
    const float* alpha  = (const float*)d_in[4];

    k_transpose_in<<<dim3(NV / 32, BB / 32), dim3(32, 32)>>>(llr);
    k_invperm<<<(EE + 255) / 256, 256>>>(edge_v);

    for (int t = 0; t < TT; t++) {
        k_check<<<MC * 2, 256>>>(edge_v, beta, t);
        k_var<<<NV * 2, 256>>>(alpha, t, (t == TT - 1) ? 1 : 0);
    }

    int mode = (out_size == 2 * BB * NV) ? 2 : 1;
    k_out<<<dim3(NV / 32, BB / 32), dim3(32, 32)>>>((float*)d_out, (int*)d_out, mode);
}

// round 2
// speedup vs baseline: 1.4600x; 1.4600x over previous
#include <cuda_runtime.h>
#include <math.h>
#include <stdint.h>

#define NV 8192      // variable nodes
#define MC 4096      // check nodes
#define DV 3         // layers
#define EE (DV*NV)   // edges = 24576
#define BB 512       // batch
#define TT 10        // iterations
#define CB 256       // batch chunk size (L2 residency: 56MB working set per chunk)
#define NCH (BB/CB)  // 2 chunks

// ---------------- device scratch (static, no allocation) ----------------
__device__ float g_llr_t[NV * BB];   // llr transposed [N, B]   16 MB
__device__ float g_v2c[EE * BB];     // v2c messages   [E, B]   48 MB
__device__ float g_c2v[EE * BB];     // c2v messages   [E, B]   48 MB
__device__ float g_post[NV * BB];    // posterior      [N, B]   16 MB
__device__ int   g_inv[DV * NV];     // inverse permutations

// ---------------- transpose llr [B,N] -> [N,B] ----------------
__global__ void k_transpose_in(const float* __restrict__ llr) {
    __shared__ float tile[32][33];
    int n0 = blockIdx.x * 32;
    int b0 = blockIdx.y * 32;
    tile[threadIdx.y][threadIdx.x] = llr[(b0 + threadIdx.y) * NV + (n0 + threadIdx.x)];
    __syncthreads();
    g_llr_t[(n0 + threadIdx.y) * BB + (b0 + threadIdx.x)] = tile[threadIdx.x][threadIdx.y];
}

// ---------------- inverse permutation build ----------------
__global__ void k_invperm(const int* __restrict__ edge_v) {
    int e = blockIdx.x * blockDim.x + threadIdx.x;
    if (e < EE) {
        int l = e >> 13;          // N = 8192 = 2^13
        int i = e & (NV - 1);
        g_inv[l * NV + edge_v[e]] = i;
    }
}

// ---------------- check-node update (float4 over batch, chunked) ----------------
// block = 256 threads = 4 checks x 64 float4-lanes (covers CB=256 batch lanes)
__global__ void __launch_bounds__(256) k_check(const int* __restrict__ edge_v,
                                               const float* __restrict__ beta,
                                               int t, int b0) {
    int m = (blockIdx.x << 2) | (threadIdx.x >> 6);
    int b = b0 + ((threadIdx.x & 63) << 2);

    float4 r[6];
    if (t == 0) {
#pragma unroll
        for (int l = 0; l < 6; l++) {
            int v = __ldg(&edge_v[(l >> 1) * NV + 2 * m + (l & 1)]);
            r[l] = *(const float4*)&g_llr_t[v * BB + b];
        }
    } else {
#pragma unroll
        for (int l = 0; l < 6; l++) {
            int e = (l >> 1) * NV + 2 * m + (l & 1);
            r[l] = *(const float4*)&g_v2c[e * BB + b];
        }
    }

    float bt = __ldg(&beta[t]);
    float4 o[6];
#pragma unroll
    for (int k = 0; k < 4; k++) {
        float m1 = INFINITY, m2 = INFINITY;
        int arg = 0, par = 0;
        bool anyzero = false;
#pragma unroll
        for (int l = 0; l < 6; l++) {
            float x = ((const float*)&r[l])[k];
            float a = fabsf(x);
            par ^= (x < 0.0f) ? 1 : 0;
            anyzero |= (a == 0.0f);
            if (a < m1) { m2 = m1; m1 = a; arg = l; }
            else if (a < m2) { m2 = a; }
        }
#pragma unroll
        for (int l = 0; l < 6; l++) {
            float x = ((const float*)&r[l])[k];
            float mag = (l == arg) ? m2 : m1;
            int neg = par ^ ((x < 0.0f) ? 1 : 0);
            float c = bt * (neg ? -mag : mag);
            if (anyzero) c = 0.0f;
            ((float*)&o[l])[k] = c;
        }
    }

#pragma unroll
    for (int l = 0; l < 6; l++) {
        int e = (l >> 1) * NV + 2 * m + (l & 1);
        *(float4*)&g_c2v[e * BB + b] = o[l];
    }
}

// ---------------- variable-node update (float4 over batch, chunked) ----------------
// block = 256 threads = 4 variables x 64 float4-lanes
__global__ void __launch_bounds__(256) k_var(const float* __restrict__ alpha,
                                             int t, int last, int b0) {
    int v = (blockIdx.x << 2) | (threadIdx.x >> 6);
    int b = b0 + ((threadIdx.x & 63) << 2);

    int e0 = 0 * NV + __ldg(&g_inv[0 * NV + v]);
    int e1 = 1 * NV + __ldg(&g_inv[1 * NV + v]);
    int e2 = 2 * NV + __ldg(&g_inv[2 * NV + v]);

    float4 c0 = *(const float4*)&g_c2v[e0 * BB + b];
    float4 c1 = *(const float4*)&g_c2v[e1 * BB + b];
    float4 c2 = *(const float4*)&g_c2v[e2 * BB + b];
    float4 lv = *(const float4*)&g_llr_t[v * BB + b];

    if (last) {
        float4 p;
#pragma unroll
        for (int k = 0; k < 4; k++) {
            float s = ((const float*)&c0)[k] + ((const float*)&c1)[k] + ((const float*)&c2)[k];
            ((float*)&p)[k] = ((const float*)&lv)[k] + s;   // posterior: no alpha
        }
        *(float4*)&g_post[v * BB + b] = p;
    } else {
        float at = __ldg(&alpha[t]);
        float4 o0, o1, o2;
#pragma unroll
        for (int k = 0; k < 4; k++) {
            float x0 = ((const float*)&c0)[k];
            float x1 = ((const float*)&c1)[k];
            float x2 = ((const float*)&c2)[k];
            float s = x0 + x1 + x2;
            float l = ((const float*)&lv)[k];
            ((float*)&o0)[k] = l + at * (s - x0);
            ((float*)&o1)[k] = l + at * (s - x1);
            ((float*)&o2)[k] = l + at * (s - x2);
        }
        *(float4*)&g_v2c[e0 * BB + b] = o0;
        *(float4*)&g_v2c[e1 * BB + b] = o1;
        *(float4*)&g_v2c[e2 * BB + b] = o2;
    }
}

// ---------------- output: transpose posterior, emit bits + posterior ----------------
__global__ void k_out(float* __restrict__ out_f, int* __restrict__ out_i, int mode) {
    __shared__ float tile[32][33];
    int n0 = blockIdx.x * 32;
    int b0 = blockIdx.y * 32;
    tile[threadIdx.y][threadIdx.x] = g_post[(n0 + threadIdx.y) * BB + (b0 + threadIdx.x)];
    __syncthreads();
    float p = tile[threadIdx.x][threadIdx.y];                // n = n0+tx, b = b0+ty
    int o = (b0 + threadIdx.y) * NV + (n0 + threadIdx.x);    // [B, N] row-major
    if (mode == 2) {
        out_f[o] = (p < 0.0f) ? 1.0f : 0.0f;   // decoded bits
        out_f[BB * NV + o] = p;                // posterior
    } else {
        out_i[o] = (p < 0.0f) ? 1 : 0;
    }
}

extern "C" void kernel_launch(void* const* d_in, const int* in_sizes, int n_in,
                              void* d_out, int out_size) {
    const float* llr    = (const float*)d_in[0];
    const int*   edge_v = (const int*)d_in[1];
    const float* beta   = (const float*)d_in[3];
    const float* alpha  = (const float*)d_in[4];

    k_transpose_in<<<dim3(NV / 32, BB / 32), dim3(32, 32)>>>(llr);
    k_invperm<<<(EE + 255) / 256, 256>>>(edge_v);

    for (int ch = 0; ch < NCH; ch++) {
        int b0 = ch * CB;
        for (int t = 0; t < TT; t++) {
            k_check<<<MC / 4, 256>>>(edge_v, beta, t, b0);
            k_var<<<NV / 4, 256>>>(alpha, t, (t == TT - 1) ? 1 : 0, b0);
        }
    }

    int mode = (out_size == 2 * BB * NV) ? 2 : 1;
    k_out<<<dim3(NV / 32, BB / 32), dim3(32, 32)>>>((float*)d_out, (int*)d_out, mode);
}